// round 1
// baseline (speedup 1.0000x reference)
#include <cuda_runtime.h>
#include <math.h>

#define BB 4
#define NN 4096
#define MM 4096
#define CCH 64
#define KK 32
#define RADIUS 0.1f
#define RAD2 0.01f
#define EPSV 1e-5f

// ---------------- device scratch (no cudaMalloc allowed) ----------------
__device__ float    g_featT[BB * MM * CCH];   // [B][M][C] transposed features
__device__ int      g_idx[BB * NN * KK];      // top-K indices per query
__device__ unsigned g_nbr[BB * NN];           // neighbor-valid bitmask (d2 <= R^2)
__device__ int      g_idxnn[BB * NN];         // nearest-neighbor index

// ---------------- kernel 0: transpose features [B,C,M] -> [B,M,C] ----------------
__global__ void k_transpose(const float* __restrict__ f) {
    int i = blockIdx.x * blockDim.x + threadIdx.x;
    if (i < BB * MM * CCH) {
        int c = i & 63;
        int m = (i >> 6) & (MM - 1);
        int b = i >> 18;
        g_featT[i] = f[(b * CCH + c) * MM + m];
    }
}

// ---------------- kernel 1: warp-bitonic top-K=32 KNN ----------------
__device__ __forceinline__ void bsort32(float& d, int& ix, int lane) {
#pragma unroll
    for (int k = 2; k <= 32; k <<= 1) {
#pragma unroll
        for (int j = k >> 1; j > 0; j >>= 1) {
            float od = __shfl_xor_sync(0xffffffffu, d, j);
            int   oi = __shfl_xor_sync(0xffffffffu, ix, j);
            bool keepMin = (((lane & k) == 0) == ((lane & j) == 0));
            bool take = keepMin ? (od < d) : (od > d);
            if (take) { d = od; ix = oi; }
        }
    }
}

__device__ __forceinline__ void bmerge32(float& d, int& ix, int lane) {
#pragma unroll
    for (int j = 16; j > 0; j >>= 1) {
        float od = __shfl_xor_sync(0xffffffffu, d, j);
        int   oi = __shfl_xor_sync(0xffffffffu, ix, j);
        bool keepMin = ((lane & j) == 0);
        bool take = keepMin ? (od < d) : (od > d);
        if (take) { d = od; ix = oi; }
    }
}

__global__ __launch_bounds__(256) void k_knn(const float* __restrict__ qxyz,
                                             const float* __restrict__ sxyz,
                                             const int* __restrict__ smask) {
    __shared__ float sx[MM], sy[MM], sz[MM];
    int b   = blockIdx.x >> 9;        // 512 blocks per batch (4096/8)
    int grp = blockIdx.x & 511;
    for (int i = threadIdx.x; i < MM; i += 256) {
        bool v = smask[b * MM + i] > 0;
        float x = sxyz[(b * MM + i) * 3 + 0];
        float y = sxyz[(b * MM + i) * 3 + 1];
        float z = sxyz[(b * MM + i) * 3 + 2];
        sx[i] = v ? x : 1e18f;
        sy[i] = v ? y : 1e18f;
        sz[i] = v ? z : 1e18f;
    }
    __syncthreads();

    int warp = threadIdx.x >> 5, lane = threadIdx.x & 31;
    int n  = grp * 8 + warp;
    int qi = b * NN + n;
    float qx = qxyz[qi * 3 + 0];
    float qy = qxyz[qi * 3 + 1];
    float qz = qxyz[qi * 3 + 2];

    float bd = INFINITY; int bi = 0;
    float thr = INFINITY;
    for (int ch = 0; ch < MM / 32; ++ch) {
        int m = ch * 32 + lane;
        float dx = qx - sx[m], dy = qy - sy[m], dz = qz - sz[m];
        float d2 = fmaf(dx, dx, fmaf(dy, dy, dz * dz));
        if (__ballot_sync(0xffffffffu, d2 < thr)) {
            float nd = d2; int ni = m;
            bsort32(nd, ni, lane);
            // merge ascending best with reversed ascending new -> K smallest of union
            float rd = __shfl_sync(0xffffffffu, nd, 31 ^ lane);
            int   ri = __shfl_sync(0xffffffffu, ni, 31 ^ lane);
            if (rd < bd) { bd = rd; bi = ri; }
            bmerge32(bd, bi, lane);      // bitonic -> ascending
            thr = __shfl_sync(0xffffffffu, bd, 31);
        }
    }
    g_idx[qi * KK + lane] = bi;
    unsigned nb = __ballot_sync(0xffffffffu, bd <= RAD2);
    if (lane == 0) { g_nbr[qi] = nb; g_idxnn[qi] = bi; }
}

// ---------------- kernel 2: fused gather + MLPs + softmax-reduce ----------------
struct P2 {
    const float *qxyz, *sxyz;
    const int   *qmask;
    const float *Wth1, *bth1, *Wth2, *bth2;
    const float *Wphi, *bphi, *Wpsi, *bpsi, *Wal, *bal;
    const float *Wg1, *bg1, *Wg2, *bg2;
    const float *gt, *bet, *rmt, *rvt, *gg, *beg, *rmg, *rvg;
    float* out;
};

#define STRD 36

constexpr int OFF_WPHI = 0;
constexpr int OFF_WPSI = 4096;
constexpr int OFF_WT2  = 8192;
constexpr int OFF_WG1  = 12288;
constexpr int OFF_WG2  = 16384;
constexpr int OFF_WAL  = 20480;
constexpr int OFF_WTH1 = 24576;   // 192
constexpr int OFF_BIAS = 24768;   // 7 * 64
constexpr int OFF_BN   = 25216;   // 4 * 64
constexpr int OFF_Q    = 25472;
constexpr int QSZ      = 12032;
constexpr int QO_XJ = 0, QO_T1 = 2304, QO_R = 4608, QO_F = 6912, QO_U = 9216;
constexpr int QO_POS = 11520, QO_FM = 11616, QO_XI = 11648, QO_RED = 11712, QO_KIDX = 11968;
constexpr int SMEM_FLOATS = OFF_Q + 2 * QSZ;   // 49536 floats = 198144 B

__global__ __launch_bounds__(512, 1) void k_main(P2 p) {
    extern __shared__ float sm[];
    int tid = threadIdx.x;

    // ---- load weights (transposed) + biases + BN constants into smem ----
    {
        const float* srcs[6] = {p.Wphi, p.Wpsi, p.Wth2, p.Wg1, p.Wg2, p.Wal};
        const int    offs[6] = {OFF_WPHI, OFF_WPSI, OFF_WT2, OFF_WG1, OFF_WG2, OFF_WAL};
#pragma unroll
        for (int w = 0; w < 6; ++w) {
            const float* s = srcs[w];
            float* d = sm + offs[w];
            for (int i = tid; i < 4096; i += 512) {
                int o = i >> 6, in = i & 63;
                d[in * 64 + o] = s[i];          // Wt[in][o] = W[o][in]
            }
        }
        for (int i = tid; i < 192; i += 512) {
            int c = i / 3, j = i - 3 * c;
            sm[OFF_WTH1 + j * 64 + c] = p.Wth1[i];
        }
        const float* bs[7] = {p.bth1, p.bth2, p.bphi, p.bpsi, p.bal, p.bg1, p.bg2};
#pragma unroll
        for (int w = 0; w < 7; ++w)
            for (int i = tid; i < 64; i += 512)
                sm[OFF_BIAS + w * 64 + i] = bs[w][i];
        for (int i = tid; i < 64; i += 512) {
            float it = p.gt[i] * rsqrtf(p.rvt[i] + EPSV);
            sm[OFF_BN + 0 * 64 + i] = it;
            sm[OFF_BN + 1 * 64 + i] = p.bet[i] - p.rmt[i] * it;
            float ig = p.gg[i] * rsqrtf(p.rvg[i] + EPSV);
            sm[OFF_BN + 2 * 64 + i] = ig;
            sm[OFF_BN + 3 * 64 + i] = p.beg[i] - p.rmg[i] * ig;
        }
    }
    __syncthreads();

    int q  = tid >> 8;     // query slot in block (0..1)
    int t  = tid & 255;
    int c  = t & 63;       // channel
    int g  = t >> 6;       // slot group (0..3), 8 k-slots each
    int k0 = g * 8;

    float* Q    = sm + OFF_Q + q * QSZ;
    float* xjB  = Q + QO_XJ;
    float* t1B  = Q + QO_T1;   // reused for rel2
    float* RB   = Q + QO_R;
    float* FB   = Q + QO_F;
    float* UB   = Q + QO_U;
    float* posB = Q + QO_POS;
    float* fmB  = Q + QO_FM;
    float* xiB  = Q + QO_XI;
    float* red  = Q + QO_RED;
    int*   kidx = (int*)(Q + QO_KIDX);

    float b_th1 = sm[OFF_BIAS + 0 * 64 + c];
    float b_th2 = sm[OFF_BIAS + 1 * 64 + c];
    float b_phi = sm[OFF_BIAS + 2 * 64 + c];
    float b_psi = sm[OFF_BIAS + 3 * 64 + c];
    float b_al  = sm[OFF_BIAS + 4 * 64 + c];
    float b_g1  = sm[OFF_BIAS + 5 * 64 + c];
    float b_g2  = sm[OFF_BIAS + 6 * 64 + c];
    float inv_t = sm[OFF_BN + 0 * 64 + c];
    float sh_t  = sm[OFF_BN + 1 * 64 + c];
    float inv_g = sm[OFF_BN + 2 * 64 + c];
    float sh_g  = sm[OFF_BN + 3 * 64 + c];
    float wt1a  = sm[OFF_WTH1 + 0 * 64 + c];
    float wt1b  = sm[OFF_WTH1 + 1 * 64 + c];
    float wt1c  = sm[OFF_WTH1 + 2 * 64 + c];

    const int npairs = (BB * NN) / 2;
    for (int pair = blockIdx.x; pair < npairs; pair += gridDim.x) {
        int qi = pair * 2 + q;
        int b  = qi >> 12;
        int n  = qi & (NN - 1);

        // ---- setup: neighbor indices, pos, fmask, x_i ----
        if (t < 32) {
            int k  = t;
            int ki = g_idx[qi * KK + k];
            kidx[k] = ki;
            float qx = p.qxyz[qi * 3 + 0];
            float qy = p.qxyz[qi * 3 + 1];
            float qz = p.qxyz[qi * 3 + 2];
            const float* s = p.sxyz + ((long)b * MM + ki) * 3;
            posB[0 * 32 + k] = (s[0] - qx) * (1.0f / RADIUS);
            posB[1 * 32 + k] = (s[1] - qy) * (1.0f / RADIUS);
            posB[2 * 32 + k] = (s[2] - qz) * (1.0f / RADIUS);
            unsigned nb = g_nbr[qi];
            int qm = p.qmask[qi];
            fmB[k] = (float)((nb >> k) & 1u) + (1.0f - (float)qm);
        } else if (t < 96) {
            int cc = t - 32;
            xiB[cc] = g_featT[((long)b * MM + g_idxnn[qi]) * 64 + cc];
        }
        __syncthreads();

        // ---- gather x_j [64][32] (coalesced 256B rows from g_featT) ----
        for (int i = t; i < 2048; i += 256) {
            int cc = i & 63, k = i >> 6;
            xjB[cc * STRD + k] = g_featT[((long)b * MM + kidx[k]) * 64 + cc];
        }
        // ---- lin_i partial (phi matvec, split over g) ----
        {
            float acc = 0.f;
            const float* Wp = sm + OFF_WPHI;
#pragma unroll
            for (int c2 = 0; c2 < 16; ++c2)
                acc = fmaf(Wp[(g * 16 + c2) * 64 + c], xiB[g * 16 + c2], acc);
            red[g * 64 + c] = acc;
        }
        // ---- t1 = theta1(pos) ----
#pragma unroll
        for (int kk = 0; kk < 8; ++kk) {
            int k = k0 + kk;
            float v = b_th1;
            v = fmaf(wt1a, posB[0 * 32 + k], v);
            v = fmaf(wt1b, posB[1 * 32 + k], v);
            v = fmaf(wt1c, posB[2 * 32 + k], v);
            t1B[c * STRD + k] = v;
        }
        __syncthreads();

        float lin_i = red[c] + red[64 + c] + red[128 + c] + red[192 + c] + b_phi;

        // ---- stage A: delta(theta2), lin_j(psi), alpha(x_j) fused ----
        float del[8], lj[8], af[8];
#pragma unroll
        for (int kk = 0; kk < 8; ++kk) { del[kk] = 0.f; lj[kk] = 0.f; af[kk] = 0.f; }
        {
            const float* W2 = sm + OFF_WT2 + c;
            const float* Wp = sm + OFF_WPSI + c;
            const float* Wa = sm + OFF_WAL + c;
            const float* tb = t1B + k0;
            const float* xb = xjB + k0;
#pragma unroll 4
            for (int c2 = 0; c2 < 64; ++c2) {
                float w2 = W2[c2 * 64], wp = Wp[c2 * 64], wa = Wa[c2 * 64];
                float4 t0 = *(const float4*)(tb + c2 * STRD);
                float4 t1v = *(const float4*)(tb + c2 * STRD + 4);
                float4 x0 = *(const float4*)(xb + c2 * STRD);
                float4 x1 = *(const float4*)(xb + c2 * STRD + 4);
                del[0] = fmaf(w2, t0.x, del[0]);  del[1] = fmaf(w2, t0.y, del[1]);
                del[2] = fmaf(w2, t0.z, del[2]);  del[3] = fmaf(w2, t0.w, del[3]);
                del[4] = fmaf(w2, t1v.x, del[4]); del[5] = fmaf(w2, t1v.y, del[5]);
                del[6] = fmaf(w2, t1v.z, del[6]); del[7] = fmaf(w2, t1v.w, del[7]);
                lj[0] = fmaf(wp, x0.x, lj[0]);  lj[1] = fmaf(wp, x0.y, lj[1]);
                lj[2] = fmaf(wp, x0.z, lj[2]);  lj[3] = fmaf(wp, x0.w, lj[3]);
                lj[4] = fmaf(wp, x1.x, lj[4]);  lj[5] = fmaf(wp, x1.y, lj[5]);
                lj[6] = fmaf(wp, x1.z, lj[6]);  lj[7] = fmaf(wp, x1.w, lj[7]);
                af[0] = fmaf(wa, x0.x, af[0]);  af[1] = fmaf(wa, x0.y, af[1]);
                af[2] = fmaf(wa, x0.z, af[2]);  af[3] = fmaf(wa, x0.w, af[3]);
                af[4] = fmaf(wa, x1.x, af[4]);  af[5] = fmaf(wa, x1.y, af[5]);
                af[6] = fmaf(wa, x1.z, af[6]);  af[7] = fmaf(wa, x1.w, af[7]);
            }
        }
#pragma unroll
        for (int kk = 0; kk < 8; ++kk) {
            int k = k0 + kk;
            float dl  = fmaxf(fmaf(del[kk] + b_th2, inv_t, sh_t), 0.f);
            float rel = lin_i - (lj[kk] + b_psi) + dl;
            float ft  = (af[kk] + b_al + dl) * fmB[k];
            RB[c * STRD + k] = rel;
            FB[c * STRD + k] = ft;
        }
        __syncthreads();

        // ---- stage B: u = gamma1(rel) ----
        float u[8];
#pragma unroll
        for (int kk = 0; kk < 8; ++kk) u[kk] = 0.f;
        {
            const float* W  = sm + OFF_WG1 + c;
            const float* rb = RB + k0;
#pragma unroll 4
            for (int c2 = 0; c2 < 64; ++c2) {
                float w = W[c2 * 64];
                float4 r0 = *(const float4*)(rb + c2 * STRD);
                float4 r1 = *(const float4*)(rb + c2 * STRD + 4);
                u[0] = fmaf(w, r0.x, u[0]); u[1] = fmaf(w, r0.y, u[1]);
                u[2] = fmaf(w, r0.z, u[2]); u[3] = fmaf(w, r0.w, u[3]);
                u[4] = fmaf(w, r1.x, u[4]); u[5] = fmaf(w, r1.y, u[5]);
                u[6] = fmaf(w, r1.z, u[6]); u[7] = fmaf(w, r1.w, u[7]);
            }
        }
#pragma unroll
        for (int kk = 0; kk < 8; ++kk)
            UB[c * STRD + k0 + kk] = u[kk] + b_g1;
        __syncthreads();

        // ---- stage C: rel2 = relu(bn(gamma2(u))) ----
        float v[8];
#pragma unroll
        for (int kk = 0; kk < 8; ++kk) v[kk] = 0.f;
        {
            const float* W  = sm + OFF_WG2 + c;
            const float* ub = UB + k0;
#pragma unroll 4
            for (int c2 = 0; c2 < 64; ++c2) {
                float w = W[c2 * 64];
                float4 u0 = *(const float4*)(ub + c2 * STRD);
                float4 u1 = *(const float4*)(ub + c2 * STRD + 4);
                v[0] = fmaf(w, u0.x, v[0]); v[1] = fmaf(w, u0.y, v[1]);
                v[2] = fmaf(w, u0.z, v[2]); v[3] = fmaf(w, u0.w, v[3]);
                v[4] = fmaf(w, u1.x, v[4]); v[5] = fmaf(w, u1.y, v[5]);
                v[6] = fmaf(w, u1.z, v[6]); v[7] = fmaf(w, u1.w, v[7]);
            }
        }
#pragma unroll
        for (int kk = 0; kk < 8; ++kk)
            t1B[c * STRD + k0 + kk] = fmaxf(fmaf(v[kk] + b_g2, inv_g, sh_g), 0.f);
        __syncthreads();

        // ---- softmax over k + weighted sum ----
        if (g == 0) {
            float mx = -INFINITY;
#pragma unroll 4
            for (int k = 0; k < 32; ++k) mx = fmaxf(mx, t1B[c * STRD + k]);
            float se = 0.f, sf = 0.f;
#pragma unroll 4
            for (int k = 0; k < 32; ++k) {
                float e = __expf(t1B[c * STRD + k] - mx);
                se += e;
                sf = fmaf(e, FB[c * STRD + k], sf);
            }
            p.out[((long)b * CCH + c) * NN + n] = sf / se;
        }
        __syncthreads();
    }
}

// ---------------- host launcher ----------------
extern "C" void kernel_launch(void* const* d_in, const int* in_sizes, int n_in,
                              void* d_out, int out_size) {
    const float* qxyz  = (const float*)d_in[0];
    const float* sxyz  = (const float*)d_in[1];
    const int*   qmask = (const int*)d_in[2];
    const int*   smask = (const int*)d_in[3];
    const float* feat  = (const float*)d_in[4];

    P2 p;
    p.qxyz = qxyz; p.sxyz = sxyz; p.qmask = qmask;
    p.Wth1 = (const float*)d_in[5];  p.bth1 = (const float*)d_in[6];
    p.Wth2 = (const float*)d_in[7];  p.bth2 = (const float*)d_in[8];
    p.Wphi = (const float*)d_in[9];  p.bphi = (const float*)d_in[10];
    p.Wpsi = (const float*)d_in[11]; p.bpsi = (const float*)d_in[12];
    p.Wal  = (const float*)d_in[13]; p.bal  = (const float*)d_in[14];
    p.Wg1  = (const float*)d_in[15]; p.bg1  = (const float*)d_in[16];
    p.Wg2  = (const float*)d_in[17]; p.bg2  = (const float*)d_in[18];
    p.gt   = (const float*)d_in[19]; p.bet  = (const float*)d_in[20];
    p.rmt  = (const float*)d_in[21]; p.rvt  = (const float*)d_in[22];
    p.gg   = (const float*)d_in[23]; p.beg  = (const float*)d_in[24];
    p.rmg  = (const float*)d_in[25]; p.rvg  = (const float*)d_in[26];
    p.out  = (float*)d_out;

    k_transpose<<<(BB * MM * CCH + 255) / 256, 256>>>(feat);
    k_knn<<<(BB * NN) / 8, 256>>>(qxyz, sxyz, smask);

    cudaFuncSetAttribute(k_main, cudaFuncAttributeMaxDynamicSharedMemorySize,
                         SMEM_FLOATS * 4);
    int dev = 0, nsm = 148;
    cudaGetDevice(&dev);
    cudaDeviceGetAttribute(&nsm, cudaDevAttrMultiProcessorCount, dev);
    k_main<<<nsm, 512, SMEM_FLOATS * 4>>>(p);
}